// round 1
// baseline (speedup 1.0000x reference)
#include <cuda_runtime.h>
#include <math.h>

// ---------------------------------------------------------------------------
// CLFormer fused implementation for GB300 (sm_103a)
//
// Shapes (fixed by the problem):
//   B=32, C=32, L=16384, HEADS=4 (dh=8), NB=3 blocks, DOUT=10
//
// Layout convention: all big activations kept in [B][C][L] (channel-major)
// so every global access is a perfectly coalesced per-channel row.
// The h buffer is updated IN PLACE by the token kernels (each thread owns
// one token: read 32 ch, compute, write 32 ch) -> only 64MB of scratch,
// which stays L2-resident across kernels.
//
// Per block:
//   - k-softmax over L needs a global reduction -> chunked partial stats
//     (online max, S[d]=sum exp, M[d][e]=sum exp*h) + tiny combine kernel
//     producing kv[b][h][8][8].
//   - token kernel: q-softmax (over dh) @ kv, FC1+GELU, FC2+GELU, and it
//     FUSES the partial-stats computation for the NEXT block (or the
//     mean-pool partials for the last block).
// ---------------------------------------------------------------------------

#define Bn   32
#define Cn   32
#define Ln   16384
#define TLn  512              // tokens per CTA (chunk)
#define NCHn (Ln / TLn)       // 32 chunks per batch row
#define NTHn 128              // threads per CTA
#define NGRPn (TLn / NTHn)    // 4 groups of 128 tokens

// Scratch (device globals; no allocation at runtime)
__device__ float g_h[(size_t)Bn * Cn * Ln];        // 64 MB activation buffer (in-place)
__device__ float g_part[Bn * NCHn * 320];          // per-(b,chunk): 32 m | 32 S | 256 M
__device__ float g_kv[Bn * 256];                   // kv[b][head][d][e]
__device__ float g_poolpart[Bn * NCHn * 32];       // pooling partial sums

__device__ __forceinline__ float gelu_f(float v) {
    return 0.5f * v * (1.0f + erff(v * 0.7071067811865475f));
}

// Shared-memory block for chunk-local softmax stats
struct StatsSh {
    float hSh[NTHn * 33];   // token-major h values (padded stride 33: conflict-free)
    float eSh[NTHn * 33];   // exp(h - chunk_max)
    float sm[32];           // running per-channel max
    float sS[32];           // running per-channel exp-sum
    float sM[256];          // running M[head][d][e]
    float snewm[32];
    float sr[32];           // rescale factors
    float wred[4 * 32];     // per-warp reduction scratch
};

__device__ __forceinline__ void stats_init(StatsSh* s, int tid) {
    if (tid < 32) { s->sm[tid] = -1e30f; s->sS[tid] = 0.f; }
    s->sM[tid] = 0.f;
    s->sM[tid + 128] = 0.f;
}

// All 128 threads participate; hv = this thread's token values (32 channels).
__device__ __forceinline__ void stats_group(StatsSh* s, const float (&hv)[32],
                                            int tid, int lane, int wid) {
    // stage token values
#pragma unroll
    for (int c = 0; c < 32; c++) s->hSh[tid * 33 + c] = hv[c];

    // per-channel max across the 128 tokens of this group
#pragma unroll
    for (int c = 0; c < 32; c++) {
        float v = hv[c];
#pragma unroll
        for (int o = 16; o > 0; o >>= 1)
            v = fmaxf(v, __shfl_xor_sync(0xffffffffu, v, o));
        if (lane == 0) s->wred[wid * 32 + c] = v;
    }
    __syncthreads();
    if (tid < 32) {
        float gm = fmaxf(fmaxf(s->wred[tid], s->wred[32 + tid]),
                         fmaxf(s->wred[64 + tid], s->wred[96 + tid]));
        float om = s->sm[tid];
        float nm = fmaxf(om, gm);
        s->sm[tid] = nm;
        s->snewm[tid] = nm;
        s->sr[tid] = __expf(om - nm);   // 0 on first group (om=-1e30)
    }
    __syncthreads();

    // exponentials
#pragma unroll
    for (int c = 0; c < 32; c++) s->eSh[tid * 33 + c] = __expf(hv[c] - s->snewm[c]);
    __syncthreads();

    // M / S accumulation: thread owns entries tid and tid+128
    {
        const int u0 = tid;
        const int cd0 = ((u0 >> 6) << 3) | ((u0 >> 3) & 7);
        const int ce0 = ((u0 >> 6) << 3) | (u0 & 7);
        const int cd1 = cd0 + 16;
        const int ce1 = ce0 + 16;
        float m0 = s->sM[u0] * s->sr[cd0];
        float m1 = s->sM[u0 + 128] * s->sr[cd1];
        float s0 = 0.f, s1 = 0.f;
#pragma unroll 4
        for (int l = 0; l < NTHn; l++) {
            float e0 = s->eSh[l * 33 + cd0];
            float e1 = s->eSh[l * 33 + cd1];
            m0 += e0 * s->hSh[l * 33 + ce0];
            m1 += e1 * s->hSh[l * 33 + ce1];
            s0 += e0;
            s1 += e1;
        }
        s->sM[u0] = m0;
        s->sM[u0 + 128] = m1;
        if ((tid & 7) == 0) {   // e==0 threads own S[cd]
            s->sS[cd0] = s->sS[cd0] * s->sr[cd0] + s0;
            s->sS[cd1] = s->sS[cd1] * s->sr[cd1] + s1;
        }
    }
    __syncthreads();
}

__device__ __forceinline__ void stats_writeout(StatsSh* s, int tid, int b, int ch) {
    float* pp = g_part + ((size_t)b * NCHn + ch) * 320;
    if (tid < 32) { pp[tid] = s->sm[tid]; pp[32 + tid] = s->sS[tid]; }
    pp[64 + tid] = s->sM[tid];
    pp[192 + tid] = s->sM[tid + 128];
}

// ---------------------------------------------------------------------------
// Kernel 1: stats over the raw input x (for block 0's kv)
// ---------------------------------------------------------------------------
__global__ __launch_bounds__(NTHn) void stats_x_kernel(const float* __restrict__ x) {
    __shared__ StatsSh s;
    int tid = threadIdx.x, lane = tid & 31, wid = tid >> 5;
    int b = blockIdx.y, ch = blockIdx.x;
    stats_init(&s, tid);
    __syncthreads();
    const float* xb = x + (size_t)b * Cn * Ln;
    for (int g = 0; g < NGRPn; g++) {
        int l = ch * TLn + g * NTHn + tid;
        float h[32];
#pragma unroll
        for (int c = 0; c < 32; c++) h[c] = xb[c * Ln + l];
        stats_group(&s, h, tid, lane, wid);
    }
    stats_writeout(&s, tid, b, ch);
}

// ---------------------------------------------------------------------------
// Kernel 2: combine chunk partials into kv[b][head][d][e]
// ---------------------------------------------------------------------------
__global__ __launch_bounds__(256) void combine_kernel() {
    int b = blockIdx.x, tid = threadIdx.x;
    __shared__ float gmax[32], Sg[32];
    const float* pb = g_part + (size_t)b * NCHn * 320;
    if (tid < 32) {
        float gm = -1e30f;
        for (int ch = 0; ch < NCHn; ch++) gm = fmaxf(gm, pb[ch * 320 + tid]);
        gmax[tid] = gm;
        float ss = 0.f;
        for (int ch = 0; ch < NCHn; ch++)
            ss += pb[ch * 320 + 32 + tid] * __expf(pb[ch * 320 + tid] - gm);
        Sg[tid] = ss;
    }
    __syncthreads();
    int cd = ((tid >> 6) << 3) | ((tid >> 3) & 7);
    float m = 0.f;
    for (int ch = 0; ch < NCHn; ch++)
        m += pb[ch * 320 + 64 + tid] * __expf(pb[ch * 320 + cd] - gmax[cd]);
    g_kv[b * 256 + tid] = m / Sg[cd];
}

// ---------------------------------------------------------------------------
// Kernel 3: per-token pass for one block.
//   FROM_X: read from x (else from g_h). LAST: accumulate pooling partials
//   instead of writing h + next-block stats.
// ---------------------------------------------------------------------------
template <bool FROM_X, bool LAST>
__global__ __launch_bounds__(NTHn) void token_kernel(
    const float* __restrict__ xin,
    const float* __restrict__ W1, const float* __restrict__ b1,
    const float* __restrict__ W2, const float* __restrict__ b2) {
    __shared__ StatsSh s;
    __shared__ float sW1[1024], sW2[1024], sb1[32], sb2[32], skv[256], spool[32];
    int tid = threadIdx.x, lane = tid & 31, wid = tid >> 5;
    int b = blockIdx.y, ch = blockIdx.x;

    for (int i = tid; i < 1024; i += NTHn) { sW1[i] = W1[i]; sW2[i] = W2[i]; }
    if (tid < 32) { sb1[tid] = b1[tid]; sb2[tid] = b2[tid]; spool[tid] = 0.f; }
    skv[tid] = g_kv[b * 256 + tid];
    skv[tid + 128] = g_kv[b * 256 + tid + 128];
    stats_init(&s, tid);
    __syncthreads();

    const float* inb = FROM_X ? (xin + (size_t)b * Cn * Ln) : (g_h + (size_t)b * Cn * Ln);
    float* outb = g_h + (size_t)b * Cn * Ln;

    for (int g = 0; g < NGRPn; g++) {
        int l = ch * TLn + g * NTHn + tid;
        float h[32];
#pragma unroll
        for (int c = 0; c < 32; c++) h[c] = inb[c * Ln + l];

        // ---- linear attention: q = softmax_dh(h); out = q @ kv (in place) ----
#pragma unroll
        for (int hd = 0; hd < 4; hd++) {
            const int base = hd * 8;
            float mx = h[base];
#pragma unroll
            for (int d = 1; d < 8; d++) mx = fmaxf(mx, h[base + d]);
            float es[8];
            float sum = 0.f;
#pragma unroll
            for (int d = 0; d < 8; d++) { es[d] = __expf(h[base + d] - mx); sum += es[d]; }
            float inv = 1.0f / sum;
            float acc[8];
#pragma unroll
            for (int e = 0; e < 8; e++) acc[e] = 0.f;
#pragma unroll
            for (int d = 0; d < 8; d++) {
                float q = es[d];
                const float4* kr = (const float4*)&skv[hd * 64 + d * 8];
                float4 k0 = kr[0], k1 = kr[1];
                acc[0] += q * k0.x; acc[1] += q * k0.y;
                acc[2] += q * k0.z; acc[3] += q * k0.w;
                acc[4] += q * k1.x; acc[5] += q * k1.y;
                acc[6] += q * k1.z; acc[7] += q * k1.w;
            }
#pragma unroll
            for (int e = 0; e < 8; e++) h[base + e] = acc[e] * inv;
        }

        // ---- FC1 + GELU ----
        float f[32];
#pragma unroll
        for (int j = 0; j < 32; j++) f[j] = sb1[j];
#pragma unroll
        for (int i = 0; i < 32; i++) {
            float ai = h[i];
            const float4* wr = (const float4*)&sW1[i * 32];
#pragma unroll
            for (int j4 = 0; j4 < 8; j4++) {
                float4 w = wr[j4];
                f[j4 * 4 + 0] += ai * w.x; f[j4 * 4 + 1] += ai * w.y;
                f[j4 * 4 + 2] += ai * w.z; f[j4 * 4 + 3] += ai * w.w;
            }
        }
#pragma unroll
        for (int j = 0; j < 32; j++) f[j] = gelu_f(f[j]);

        // ---- FC2 + GELU ----
#pragma unroll
        for (int j = 0; j < 32; j++) h[j] = sb2[j];
#pragma unroll
        for (int i = 0; i < 32; i++) {
            float ai = f[i];
            const float4* wr = (const float4*)&sW2[i * 32];
#pragma unroll
            for (int j4 = 0; j4 < 8; j4++) {
                float4 w = wr[j4];
                h[j4 * 4 + 0] += ai * w.x; h[j4 * 4 + 1] += ai * w.y;
                h[j4 * 4 + 2] += ai * w.z; h[j4 * 4 + 3] += ai * w.w;
            }
        }
#pragma unroll
        for (int j = 0; j < 32; j++) h[j] = gelu_f(h[j]);

        if (!LAST) {
            // write new h (in place) + fused next-block stats
#pragma unroll
            for (int c = 0; c < 32; c++) outb[c * Ln + l] = h[c];
            stats_group(&s, h, tid, lane, wid);
        } else {
            // fused mean-pool partials
#pragma unroll
            for (int c = 0; c < 32; c++) {
                float v = h[c];
#pragma unroll
                for (int o = 16; o > 0; o >>= 1)
                    v += __shfl_xor_sync(0xffffffffu, v, o);
                if (lane == 0) s.wred[wid * 32 + c] = v;
            }
            __syncthreads();
            if (tid < 32)
                spool[tid] += s.wred[tid] + s.wred[32 + tid] +
                              s.wred[64 + tid] + s.wred[96 + tid];
            __syncthreads();
        }
    }
    if (!LAST)
        stats_writeout(&s, tid, b, ch);
    else if (tid < 32)
        g_poolpart[((size_t)b * NCHn + ch) * 32 + tid] = spool[tid];
}

// ---------------------------------------------------------------------------
// Kernel 4: classifier head (pool-finish, Linear, BN(eval), GELU, Linear)
// ---------------------------------------------------------------------------
__global__ __launch_bounds__(32) void final_kernel(
    const float* __restrict__ Wh, const float* __restrict__ bh,
    const float* __restrict__ gamma, const float* __restrict__ beta,
    const float* __restrict__ mu, const float* __restrict__ var,
    const float* __restrict__ Wf, const float* __restrict__ bf,
    float* __restrict__ out) {
    int b = threadIdx.x;
    if (b >= Bn) return;
    float p[32];
#pragma unroll
    for (int c = 0; c < 32; c++) {
        float sum = 0.f;
        for (int ch = 0; ch < NCHn; ch++)
            sum += g_poolpart[((size_t)b * NCHn + ch) * 32 + c];
        p[c] = sum * (1.0f / (float)Ln);
    }
    float z[32];
#pragma unroll
    for (int j = 0; j < 32; j++) {
        float sv = bh[j];
#pragma unroll
        for (int c = 0; c < 32; c++) sv += p[c] * Wh[c * 32 + j];
        sv = (sv - mu[j]) * rsqrtf(var[j] + 1e-5f) * gamma[j] + beta[j];
        z[j] = gelu_f(sv);
    }
    for (int k = 0; k < 10; k++) {
        float sv = bf[k];
#pragma unroll
        for (int j = 0; j < 32; j++) sv += z[j] * Wf[j * 10 + k];
        out[b * 10 + k] = sv;
    }
}

// ---------------------------------------------------------------------------
// Launcher
// ---------------------------------------------------------------------------
extern "C" void kernel_launch(void* const* d_in, const int* in_sizes, int n_in,
                              void* d_out, int out_size) {
    const float* x    = (const float*)d_in[0];
    const float* fcW1 = (const float*)d_in[1];   // [3][32][32]
    const float* fcb1 = (const float*)d_in[2];   // [3][32]
    const float* fcW2 = (const float*)d_in[3];
    const float* fcb2 = (const float*)d_in[4];
    const float* Wh   = (const float*)d_in[5];
    const float* bh   = (const float*)d_in[6];
    const float* gam  = (const float*)d_in[7];
    const float* bet  = (const float*)d_in[8];
    const float* mu   = (const float*)d_in[9];
    const float* var  = (const float*)d_in[10];
    const float* Wf   = (const float*)d_in[11];
    const float* bf   = (const float*)d_in[12];
    float* out = (float*)d_out;

    dim3 grid(NCHn, Bn);

    // block 0 stats from x
    stats_x_kernel<<<grid, NTHn>>>(x);
    combine_kernel<<<Bn, 256>>>();
    // block 0 token pass (reads x, writes g_h, stats for block 1)
    token_kernel<true, false><<<grid, NTHn>>>(x, fcW1, fcb1, fcW2, fcb2);
    combine_kernel<<<Bn, 256>>>();
    // block 1 (in-place on g_h, stats for block 2)
    token_kernel<false, false><<<grid, NTHn>>>(nullptr, fcW1 + 1024, fcb1 + 32,
                                               fcW2 + 1024, fcb2 + 32);
    combine_kernel<<<Bn, 256>>>();
    // block 2 (pooling partials)
    token_kernel<false, true><<<grid, NTHn>>>(nullptr, fcW1 + 2048, fcb1 + 64,
                                              fcW2 + 2048, fcb2 + 64);
    final_kernel<<<1, 32>>>(Wh, bh, gam, bet, mu, var, Wf, bf, out);
}